// round 15
// baseline (speedup 1.0000x reference)
#include <cuda_runtime.h>
#include <cuda_bf16.h>
#include <cuda_fp16.h>
#include <math.h>
#include <stdint.h>

#define NE 200000
#define NN 10000
typedef unsigned short ushort_t;

// ---------------- scratch ----------------
__device__ float gS[NN * 128];
__device__ float gV[NN * 384];                       // [n][m][u]
__device__ ushort_t gTH[(size_t)NE * 512];           // tpw fp16; only cols 256..511 used
__device__ ushort_t gW2H[64 * 64],  gW2L[64 * 64];
__device__ ushort_t gW3H[64 * 64],  gW3L[64 * 64];
__device__ ushort_t gW4H[512 * 64], gW4L[512 * 64];
__device__ ushort_t gWsH[128 * 256];
__device__ ushort_t gWvH[128 * 256];
__device__ int gIdx64;

// ---------------- helpers ----------------
__device__ __forceinline__ uint32_t smem_u32(const void* p) {
    uint32_t a;
    asm("{ .reg .u64 t; cvta.to.shared.u64 t, %1; cvt.u32.u64 %0, t; }" : "=r"(a) : "l"(p));
    return a;
}
__device__ __forceinline__ void split_bf(float x, ushort_t& h, ushort_t& l) {
    __nv_bfloat16 hb = __float2bfloat16_rn(x);
    float r = x - __bfloat162float(hb);
    __nv_bfloat16 lb = __float2bfloat16_rn(r);
    h = *(ushort_t*)&hb; l = *(ushort_t*)&lb;
}
__device__ __forceinline__ ushort_t fp16q(float x) {
    __half hb = __float2half_rn(x);
    return *(ushort_t*)&hb;
}
__device__ __forceinline__ float fp2f(ushort_t u) {
    __half b = *(__half*)&u;
    return __half2float(b);
}
__device__ __forceinline__ void mma_bf16(float c[4], const unsigned a[4], const unsigned b[2]) {
    asm volatile("mma.sync.aligned.m16n8k16.row.col.f32.bf16.bf16.f32 "
        "{%0,%1,%2,%3}, {%4,%5,%6,%7}, {%8,%9}, {%0,%1,%2,%3};\n"
        : "+f"(c[0]), "+f"(c[1]), "+f"(c[2]), "+f"(c[3])
        : "r"(a[0]), "r"(a[1]), "r"(a[2]), "r"(a[3]), "r"(b[0]), "r"(b[1]));
}
__device__ __forceinline__ void mma_f16(float c[4], const unsigned a[4], const unsigned b[2]) {
    asm volatile("mma.sync.aligned.m16n8k16.row.col.f32.f16.f16.f32 "
        "{%0,%1,%2,%3}, {%4,%5,%6,%7}, {%8,%9}, {%0,%1,%2,%3};\n"
        : "+f"(c[0]), "+f"(c[1]), "+f"(c[2]), "+f"(c[3])
        : "r"(a[0]), "r"(a[1]), "r"(a[2]), "r"(a[3]), "r"(b[0]), "r"(b[1]));
}
__device__ __forceinline__ void ldsm4(unsigned r[4], uint32_t addr) {
    asm volatile("ldmatrix.sync.aligned.m8n8.x4.shared.b16 {%0,%1,%2,%3}, [%4];"
        : "=r"(r[0]), "=r"(r[1]), "=r"(r[2]), "=r"(r[3]) : "r"(addr));
}

// ---------------- merged weight prep (blockIdx.y selects weight) ----------------
__global__ void prep_all(const float* __restrict__ W2, const float* __restrict__ W3,
                         const float* __restrict__ W4, const float* __restrict__ Ws,
                         const float* __restrict__ Wv) {
    int y = blockIdx.y;
    const float* W; ushort_t *Th, *Tl; int Kd, Nd, f16;
    switch (y) {
        case 0:  W = W2; Th = gW2H; Tl = gW2L; Kd = 64;  Nd = 64;  f16 = 0; break;
        case 1:  W = W3; Th = gW3H; Tl = gW3L; Kd = 64;  Nd = 64;  f16 = 0; break;
        case 2:  W = W4; Th = gW4H; Tl = gW4L; Kd = 64;  Nd = 512; f16 = 0; break;
        case 3:  W = Ws; Th = gWsH; Tl = nullptr; Kd = 256; Nd = 128; f16 = 1; break;
        default: W = Wv; Th = gWvH; Tl = nullptr; Kd = 256; Nd = 128; f16 = 1; break;
    }
    int idx = blockIdx.x * 256 + threadIdx.x;
    if (idx >= Kd * Nd) return;
    int n = idx / Kd, k = idx - n * Kd;
    float x = W[(size_t)k * Nd + n];
    if (f16) {
        Th[(size_t)n * Kd + k] = fp16q(x);
    } else {
        ushort_t h, l; split_bf(x, h, l);
        Th[(size_t)n * Kd + k] = h;
        Tl[(size_t)n * Kd + k] = l;
    }
}

// ---------------- idx dtype detector ----------------
__global__ void detect_idx_kernel(const int* __restrict__ idx32) {
    if (threadIdx.x == 0) {
        int any = 0;
        for (int i = 1; i < 256; i += 2) any |= (idx32[i] != 0);
        gIdx64 = (any == 0) ? 1 : 0;
    }
}

// ---------------- merged node up-projections (blockIdx.z selects) --------------
__global__ void node_up(const float* __restrict__ NF,
                        const float* __restrict__ Wus, const float* __restrict__ Wuv) {
    const int BM = 64, BN = 64, BK = 16;
    __shared__ unsigned long long As2[BK][BM];
    __shared__ __align__(16) float Bs[BK][BN];
    int z = blockIdx.z;
    int veca = (z == 0);
    int offA = veca ? 0 : 128 + (z - 1);
    int sA = veca ? 1 : 3;
    const float* B = veca ? Wus : Wuv;
    float* Cp = veca ? gS : gV;
    int ldc = veca ? 128 : 384;
    int offC = veca ? 0 : (z - 1) * 128;
    const float scale = 0.08838834764831845f;

    int tid = threadIdx.x;
    int tx = tid & 15, ty = tid >> 4;
    int row0 = blockIdx.x * BM, col0 = blockIdx.y * BN;
    unsigned long long acc[4][2];
#pragma unroll
    for (int i = 0; i < 4; i++) { acc[i][0] = 0ull; acc[i][1] = 0ull; }
    int la_m = tid >> 2, la_k = (tid & 3) * 4;
    int lb_k = tid >> 4, lb_n = (tid & 15) * 4;
    for (int kt = 0; kt < 128; kt += BK) {
        float a0 = 0.f, a1 = 0.f, a2 = 0.f, a3 = 0.f;
        int r = row0 + la_m;
        if (r < NN) {
            if (veca) {
                float4 v4 = *(const float4*)(NF + (size_t)r * 512 + kt + la_k);
                a0 = v4.x; a1 = v4.y; a2 = v4.z; a3 = v4.w;
            } else {
                const float* p = NF + (size_t)r * 512 + offA + (size_t)(kt + la_k) * 3;
                a0 = p[0]; a1 = p[3]; a2 = p[6]; a3 = p[9];
            }
        }
        {
            unsigned long long t;
            unsigned u0 = __float_as_uint(a0);
            asm("mov.b64 %0, {%1, %1};" : "=l"(t) : "r"(u0)); As2[la_k + 0][la_m] = t;
            unsigned u1 = __float_as_uint(a1);
            asm("mov.b64 %0, {%1, %1};" : "=l"(t) : "r"(u1)); As2[la_k + 1][la_m] = t;
            unsigned u2 = __float_as_uint(a2);
            asm("mov.b64 %0, {%1, %1};" : "=l"(t) : "r"(u2)); As2[la_k + 2][la_m] = t;
            unsigned u3 = __float_as_uint(a3);
            asm("mov.b64 %0, {%1, %1};" : "=l"(t) : "r"(u3)); As2[la_k + 3][la_m] = t;
        }
        *(float4*)&Bs[lb_k][lb_n] = *(const float4*)(B + (size_t)(kt + lb_k) * 128 + col0 + lb_n);
        __syncthreads();
#pragma unroll
        for (int kk = 0; kk < BK; kk++) {
            ulonglong2 b01 = *(const ulonglong2*)&Bs[kk][tx * 4];
            unsigned long long av[4];
#pragma unroll
            for (int i = 0; i < 4; i++) av[i] = As2[kk][ty * 4 + i];
#pragma unroll
            for (int i = 0; i < 4; i++) {
                asm("fma.rn.f32x2 %0, %1, %2, %0;" : "+l"(acc[i][0]) : "l"(av[i]), "l"(b01.x));
                asm("fma.rn.f32x2 %0, %1, %2, %0;" : "+l"(acc[i][1]) : "l"(av[i]), "l"(b01.y));
            }
        }
        __syncthreads();
    }
#pragma unroll
    for (int i = 0; i < 4; i++) {
        int r = row0 + ty * 4 + i;
        if (r >= NN) continue;
#pragma unroll
        for (int jp = 0; jp < 2; jp++) {
            unsigned lo, hi;
            asm("mov.b64 {%0, %1}, %2;" : "=r"(lo), "=r"(hi) : "l"(acc[i][jp]));
            int c0 = col0 + tx * 4 + jp * 2;
            Cp[(size_t)r * ldc + offC + c0]     = __uint_as_float(lo) * scale;
            Cp[(size_t)r * ldc + offC + c0 + 1] = __uint_as_float(hi) * scale;
        }
    }
}

// ---------------- fused: edge MLP -> W4; cols<256 feed out_s in-kernel ----------
#define FUSE_SMEM 82432
__global__ __launch_bounds__(256, 1) void mlp_outs_fused(
        const float* __restrict__ EF, const float* __restrict__ W1,
        const void* __restrict__ eidx, const float* __restrict__ eattr,
        float* __restrict__ C, float cstv) {
    const int PK = 72;
    const int RB = PK * 2;
    extern __shared__ __align__(16) char sm[];
    float* sEF = (float*)sm;
    float* sW1 = (float*)(sm + 4096);
    ushort_t (*Ah)[PK] = (ushort_t(*)[PK])(sm + 6144);
    ushort_t (*Al)[PK] = (ushort_t(*)[PK])(sm + 24576);
    ushort_t (*Ao)[PK] = (ushort_t(*)[PK])(sm + 43008);
    ushort_t (*Bw)[PK] = (ushort_t(*)[PK])(sm + 61440);
    int*    sSnd = (int*)(sm + 79872);
    float4* sY   = (float4*)(sm + 80384);

    int tid = threadIdx.x, wid = tid >> 5, lane = tid & 31;
    int warp_m = wid & 3, warp_n = wid >> 2;
    int g = lane >> 2, tg = lane & 3;
    int row0 = blockIdx.x * 128;
    int am = warp_m * 32, bn = warp_n * 32;

    {
        int r = tid >> 1, hf = tid & 1;
        int e = min(row0 + r, NE - 1);
        *(float4*)&sEF[r * 8 + hf * 4] = *(const float4*)(EF + (size_t)e * 8 + hf * 4);
        if (tid < 128) *(float4*)&sW1[tid * 4] = *(const float4*)(W1 + tid * 4);
        if (tid < 128) {
            int ee = min(row0 + tid, NE - 1);
            int snd = gIdx64 ? (int)((const long long*)eidx)[ee] : ((const int*)eidx)[ee];
            sSnd[tid] = min(max(snd, 0), NN - 1);
            sY[tid] = *(const float4*)(eattr + 4 * ee);
        }
    }
    __syncthreads();

    {
        int r = tid >> 1, hf = tid & 1;
        float ef[8];
#pragma unroll
        for (int k = 0; k < 8; k++) ef[k] = sEF[r * 8 + k];
#pragma unroll
        for (int c0 = 0; c0 < 32; c0 += 2) {
            int c = hf * 32 + c0;
            float x0 = 0.f, x1 = 0.f;
#pragma unroll
            for (int k = 0; k < 8; k++) {
                x0 += ef[k] * sW1[k * 64 + c];
                x1 += ef[k] * sW1[k * 64 + c + 1];
            }
            x0 *= 0.35355339059327373f; x1 *= 0.35355339059327373f;
            x0 = x0 / (1.f + __expf(-x0)) * cstv;
            x1 = x1 / (1.f + __expf(-x1)) * cstv;
            ushort_t h0, l0, h1, l1;
            split_bf(x0, h0, l0); split_bf(x1, h1, l1);
            ushort2 ph; ph.x = h0; ph.y = h1;
            ushort2 pl; pl.x = l0; pl.y = l1;
            *(ushort2*)&Ah[r][c] = ph;
            *(ushort2*)&Al[r][c] = pl;
        }
    }

    int arow = (lane & 7) + ((lane >> 3) & 1) * 8;
    int acol = (lane >> 4) * 8;
    uint32_t aH = smem_u32(&Ah[am + arow][acol]);
    uint32_t aL = smem_u32(&Al[am + arow][acol]);
    uint32_t aO = smem_u32(&Ao[am + arow][acol]);
    int brow = (lane & 7) + ((lane >> 4) & 1) * 8;
    int bcol = ((lane >> 3) & 1) * 8;
    uint32_t bH = smem_u32(&Bw[bn + brow][bcol]);
    uint32_t bL = bH + 64 * RB;

    float acc[2][4][4];
    float acco[2][2][4][4];
#pragma unroll
    for (int n2 = 0; n2 < 2; n2++)
#pragma unroll
        for (int mt = 0; mt < 2; mt++)
#pragma unroll
            for (int nt = 0; nt < 4; nt++)
#pragma unroll
                for (int j = 0; j < 4; j++) acco[n2][mt][nt][j] = 0.f;

    auto zacc = [&] {
#pragma unroll
        for (int mt = 0; mt < 2; mt++)
#pragma unroll
            for (int nt = 0; nt < 4; nt++)
#pragma unroll
                for (int j = 0; j < 4; j++) acc[mt][nt][j] = 0.f;
    };
    auto stageB = [&](const ushort_t* TH, const ushort_t* TL, int n0) {
#pragma unroll
        for (int i = 0; i < 2; i++) {
            int idx = tid + i * 256;
            int r = idx >> 3, c8 = (idx & 7) * 8;
            *(uint4*)&Bw[r][c8] = *(const uint4*)(TH + (size_t)(n0 + r) * 64 + c8);
            *(uint4*)&Bw[r + 64][c8] = *(const uint4*)(TL + (size_t)(n0 + r) * 64 + c8);
        }
    };
    auto mmaAB = [&] {
#pragma unroll
        for (int ks = 0; ks < 4; ks++) {
            unsigned ah[2][4], al[2][4], bh[2][4], bl[2][4];
#pragma unroll
            for (int mt = 0; mt < 2; mt++) {
                ldsm4(ah[mt], aH + mt * (16 * RB) + ks * 32);
                ldsm4(al[mt], aL + mt * (16 * RB) + ks * 32);
            }
#pragma unroll
            for (int np = 0; np < 2; np++) {
                ldsm4(bh[np], bH + np * (16 * RB) + ks * 32);
                ldsm4(bl[np], bL + np * (16 * RB) + ks * 32);
            }
#pragma unroll
            for (int mt = 0; mt < 2; mt++)
#pragma unroll
                for (int nt = 0; nt < 4; nt++)
                    mma_bf16(acc[mt][nt], ah[mt], &bh[nt >> 1][(nt & 1) * 2]);
#pragma unroll
            for (int mt = 0; mt < 2; mt++)
#pragma unroll
                for (int nt = 0; nt < 4; nt++)
                    mma_bf16(acc[mt][nt], ah[mt], &bl[nt >> 1][(nt & 1) * 2]);
#pragma unroll
            for (int mt = 0; mt < 2; mt++)
#pragma unroll
                for (int nt = 0; nt < 4; nt++)
                    mma_bf16(acc[mt][nt], al[mt], &bh[nt >> 1][(nt & 1) * 2]);
        }
    };
    auto epiH = [&](float scale) {
#pragma unroll
        for (int mt = 0; mt < 2; mt++) {
            int r1 = am + mt * 16 + g, r2 = r1 + 8;
#pragma unroll
            for (int nt = 0; nt < 4; nt++) {
                int cc = bn + nt * 8 + tg * 2;
                float xs[4];
#pragma unroll
                for (int j = 0; j < 4; j++) {
                    float x = acc[mt][nt][j] * scale;
                    xs[j] = x / (1.f + __expf(-x)) * cstv;
                }
                ushort_t h0, l0, h1, l1;
                split_bf(xs[0], h0, l0); split_bf(xs[1], h1, l1);
                ushort2 ph; ph.x = h0; ph.y = h1;
                ushort2 pl; pl.x = l0; pl.y = l1;
                *(ushort2*)&Ah[r1][cc] = ph; *(ushort2*)&Al[r1][cc] = pl;
                split_bf(xs[2], h0, l0); split_bf(xs[3], h1, l1);
                ph.x = h0; ph.y = h1; pl.x = l0; pl.y = l1;
                *(ushort2*)&Ah[r2][cc] = ph; *(ushort2*)&Al[r2][cc] = pl;
            }
        }
    };

    const float inv64 = 0.125f;
    stageB(gW2H, gW2L, 0);
    __syncthreads();
    zacc(); mmaAB();
    __syncthreads();
    epiH(inv64);
    stageB(gW3H, gW3L, 0);
    __syncthreads();
    zacc(); mmaAB();
    __syncthreads();
    epiH(inv64);
    __syncthreads();

    int pr = tid >> 3, pc8 = (tid & 7) * 8;
    int pr2 = (tid + 256) >> 3, pc82 = ((tid + 256) & 7) * 8;
    uint4 pbh0, pbl0, pbh1, pbl1;
    auto loadB4 = [&](int n0) {
        pbh0 = *(const uint4*)(gW4H + (size_t)(n0 + pr) * 64 + pc8);
        pbl0 = *(const uint4*)(gW4L + (size_t)(n0 + pr) * 64 + pc8);
        pbh1 = *(const uint4*)(gW4H + (size_t)(n0 + pr2) * 64 + pc82);
        pbl1 = *(const uint4*)(gW4L + (size_t)(n0 + pr2) * 64 + pc82);
    };
    loadB4(0);
    for (int n0 = 0; n0 < 512; n0 += 64) {
        *(uint4*)&Bw[pr][pc8] = pbh0;   *(uint4*)&Bw[pr + 64][pc8] = pbl0;
        *(uint4*)&Bw[pr2][pc82] = pbh1; *(uint4*)&Bw[pr2 + 64][pc82] = pbl1;
        __syncthreads();
        if (n0 + 64 < 512) loadB4(n0 + 64);
        zacc(); mmaAB();

        if (n0 < 256) {
            __syncthreads();
#pragma unroll
            for (int mt = 0; mt < 2; mt++) {
#pragma unroll
                for (int hrow = 0; hrow < 2; hrow++) {
                    int rloc = am + mt * 16 + g + hrow * 8;
                    int snd = sSnd[rloc];
                    float4 y = sY[rloc];
#pragma unroll
                    for (int nt = 0; nt < 4; nt++) {
                        int cc = bn + nt * 8 + tg * 2;
                        int k = n0 + cc;
                        float f0, f1;
                        if (n0 < 128) {
                            const float* sp = gS + (size_t)snd * 128 + k;
                            f0 = sp[0] * y.x; f1 = sp[1] * y.x;
                        } else {
                            int u = k - 128;
                            const float* vp = gV + (size_t)snd * 384 + u;
                            f0 = (vp[0] * y.y + vp[128] * y.z + vp[256] * y.w) * 0.57735026918962576f;
                            f1 = (vp[1] * y.y + vp[129] * y.z + vp[257] * y.w) * 0.57735026918962576f;
                        }
                        float a0 = acc[mt][nt][2 * hrow + 0] * inv64 * f0;
                        float a1 = acc[mt][nt][2 * hrow + 1] * inv64 * f1;
                        ushort2 p; p.x = fp16q(a0); p.y = fp16q(a1);
                        *(ushort2*)&Ao[rloc][cc] = p;
                    }
                }
            }
#pragma unroll
            for (int i = 0; i < 4; i++) {
                int idx = tid + i * 256;
                int r = idx >> 3, c8 = (idx & 7) * 8;
                *(uint4*)&Bw[r][c8] = *(const uint4*)(gWsH + (size_t)r * 256 + n0 + c8);
            }
            __syncthreads();
#pragma unroll
            for (int ks = 0; ks < 4; ks++) {
                unsigned ah[2][4];
#pragma unroll
                for (int mt = 0; mt < 2; mt++)
                    ldsm4(ah[mt], aO + mt * (16 * RB) + ks * 32);
#pragma unroll
                for (int n2 = 0; n2 < 2; n2++) {
                    unsigned bh[2][4];
#pragma unroll
                    for (int np = 0; np < 2; np++)
                        ldsm4(bh[np], bH + n2 * (64 * RB) + np * (16 * RB) + ks * 32);
#pragma unroll
                    for (int mt = 0; mt < 2; mt++)
#pragma unroll
                        for (int nt = 0; nt < 4; nt++)
                            mma_f16(acco[n2][mt][nt], ah[mt], &bh[nt >> 1][(nt & 1) * 2]);
                }
            }
            __syncthreads();
        } else {
#pragma unroll
            for (int mt = 0; mt < 2; mt++) {
                int r1 = row0 + am + mt * 16 + g, r2 = r1 + 8;
#pragma unroll
                for (int nt = 0; nt < 4; nt++) {
                    int cc = bn + nt * 8 + tg * 2;
                    if (r1 < NE) {
                        ushort2 p; p.x = fp16q(acc[mt][nt][0] * inv64);
                        p.y = fp16q(acc[mt][nt][1] * inv64);
                        *(ushort2*)&gTH[(size_t)r1 * 512 + n0 + cc] = p;
                    }
                    if (r2 < NE) {
                        ushort2 p; p.x = fp16q(acc[mt][nt][2] * inv64);
                        p.y = fp16q(acc[mt][nt][3] * inv64);
                        *(ushort2*)&gTH[(size_t)r2 * 512 + n0 + cc] = p;
                    }
                }
            }
            __syncthreads();
        }
    }

#pragma unroll
    for (int n2 = 0; n2 < 2; n2++) {
#pragma unroll
        for (int mt = 0; mt < 2; mt++) {
            int rr[2]; rr[0] = row0 + am + mt * 16 + g; rr[1] = rr[0] + 8;
#pragma unroll
            for (int nt = 0; nt < 4; nt++) {
                int cc = n2 * 64 + bn + nt * 8 + tg * 2;
#pragma unroll
                for (int h = 0; h < 2; h++) {
                    int gr = rr[h];
                    if (gr >= NE) continue;
                    float x0 = acco[n2][mt][nt][2 * h] * 0.0625f;
                    float x1 = acco[n2][mt][nt][2 * h + 1] * 0.0625f;
                    *(float2*)&C[(size_t)gr * 512 + cc] = make_float2(x0, x1);
                }
            }
        }
    }
}

// ---------------- fused out_v: smem-staged coalesced epilogue ------------------
// dynamic smem: [0, 10240) Ah | [10240, 20480) Bhs  (mainloop)
//               [0, 67584) sOut fp32[128][132]       (epilogue, overlaps)
//               [67584] sSnd, [68096] sY0, [68608] sYm ; total 69120
#define OUTV_SMEM 69120
__global__ __launch_bounds__(256, 2) void mma_outv(
        const void* __restrict__ eidx, const float* __restrict__ eattr,
        float* __restrict__ C) {
    const int PK = 40;
    extern __shared__ __align__(16) char dsm[];
    ushort_t (*Ah)[PK] = (ushort_t(*)[PK])dsm;
    ushort_t (*Bhs)[PK] = (ushort_t(*)[PK])(dsm + 10240);
    float* sOut = (float*)dsm;
    int*   sSnd = (int*)(dsm + 67584);
    float* sY0  = (float*)(dsm + 68096);
    float* sYm  = (float*)(dsm + 68608);

    int tid = threadIdx.x;
    int wid = tid >> 5, lane = tid & 31;
    int warp_m = wid & 3, warp_n = wid >> 2;
    int g = lane >> 2, tg = lane & 3;
    int row0 = blockIdx.x * 128;
    int am = warp_m * 32, bn = warp_n * 32;

    if (tid < 128) {
        int gr = min(row0 + tid, 3 * NE - 1);
        int e = gr / 3, m = gr - 3 * e;
        int snd = gIdx64 ? (int)((const long long*)eidx)[e] : ((const int*)eidx)[e];
        sSnd[tid] = min(max(snd, 0), NN - 1);
        float4 y = *(const float4*)(eattr + 4 * e);
        sY0[tid] = y.x;
        sYm[tid] = (m == 0) ? y.y : ((m == 1) ? y.z : y.w);
    }
    __syncthreads();

    int arow = (lane & 7) + ((lane >> 3) & 1) * 8;
    int acol = (lane >> 4) * 8;
    uint32_t aH = smem_u32(&Ah[am + arow][acol]);
    int brow = (lane & 7) + ((lane >> 4) & 1) * 8;
    int bcol = ((lane >> 3) & 1) * 8;
    uint32_t bH = smem_u32(&Bhs[bn + brow][bcol]);

    float acc[2][2][4][4];
#pragma unroll
    for (int n2 = 0; n2 < 2; n2++)
#pragma unroll
        for (int mt = 0; mt < 2; mt++)
#pragma unroll
            for (int nt = 0; nt < 4; nt++)
#pragma unroll
                for (int j = 0; j < 4; j++) acc[n2][mt][nt][j] = 0.f;

    int r = tid >> 1, half = tid & 1;
    int grr = min(row0 + r, 3 * NE - 1);
    int e = grr / 3, m = grr - 3 * e;
    int snd = sSnd[r];
    float y0 = sY0[r], ym = sYm[r];

    auto computeA = [&](int kc, ushort_t* hh) {
        int u0 = (kc & 3) * 32 + half * 16;
        size_t tb = (size_t)e * 512 + (kc < 4 ? 256 : 384) + u0;
        __align__(16) ushort_t th[16];
        *(uint4*)&th[0] = *(const uint4*)(gTH + tb);
        *(uint4*)&th[8] = *(const uint4*)(gTH + tb + 8);
        if (kc < 4) {
            const float* sp = gS + (size_t)snd * 128 + u0;
#pragma unroll
            for (int j = 0; j < 16; j++)
                hh[j] = fp16q(fp2f(th[j]) * sp[j] * ym);
        } else {
            const float* vp = gV + (size_t)snd * 384 + m * 128 + u0;
#pragma unroll
            for (int j = 0; j < 16; j++)
                hh[j] = fp16q(fp2f(th[j]) * y0 * vp[j]);
        }
    };

    __align__(16) ushort_t hc[16], hn[16];
    computeA(0, hc);

    for (int kc = 0; kc < 8; kc++) {
        *(uint4*)&Ah[r][half * 16] = *(uint4*)&hc[0];
        *(uint4*)&Ah[r][half * 16 + 8] = *(uint4*)&hc[8];
        {
            const ushort_t* ph = gWvH + (size_t)r * 256 + kc * 32 + half * 16;
            *(uint4*)&Bhs[r][half * 16] = *(const uint4*)ph;
            *(uint4*)&Bhs[r][half * 16 + 8] = *(const uint4*)(ph + 8);
        }
        __syncthreads();
        if (kc < 7) computeA(kc + 1, hn);

#pragma unroll
        for (int ks = 0; ks < 2; ks++) {
            unsigned ah[2][4];
#pragma unroll
            for (int mt = 0; mt < 2; mt++)
                ldsm4(ah[mt], aH + mt * (16 * PK * 2) + ks * 32);
#pragma unroll
            for (int n2 = 0; n2 < 2; n2++) {
                unsigned bh[2][4];
#pragma unroll
                for (int np = 0; np < 2; np++)
                    ldsm4(bh[np], bH + n2 * (64 * PK * 2) + np * (16 * PK * 2) + ks * 32);
#pragma unroll
                for (int mt = 0; mt < 2; mt++)
#pragma unroll
                    for (int nt = 0; nt < 4; nt++)
                        mma_f16(acc[n2][mt][nt], ah[mt], &bh[nt >> 1][(nt & 1) * 2]);
            }
        }
        __syncthreads();
#pragma unroll
        for (int j = 0; j < 16; j++) hc[j] = hn[j];
    }

    // ---- epilogue: stage fp32 tile to smem, then coalesced writes ----
#pragma unroll
    for (int n2 = 0; n2 < 2; n2++) {
#pragma unroll
        for (int mt = 0; mt < 2; mt++) {
            int rl0 = am + mt * 16 + g, rl1 = rl0 + 8;
#pragma unroll
            for (int nt = 0; nt < 4; nt++) {
                int cc = n2 * 64 + bn + nt * 8 + tg * 2;
                *(float2*)&sOut[rl0 * 132 + cc] =
                    make_float2(acc[n2][mt][nt][0] * 0.0625f, acc[n2][mt][nt][1] * 0.0625f);
                *(float2*)&sOut[rl1 * 132 + cc] =
                    make_float2(acc[n2][mt][nt][2] * 0.0625f, acc[n2][mt][nt][3] * 0.0625f);
            }
        }
    }
    __syncthreads();
    int e0 = row0 / 3;
    for (int d = tid; d < 44 * 384; d += 256) {
        int ee = e0 + d / 384, j = d - (d / 384) * 384;
        int mm = j - (j / 3) * 3;
        int rloc = 3 * ee + mm - row0;
        if (rloc >= 0 && rloc < 128 && ee < NE)
            C[(size_t)ee * 512 + 128 + j] = sOut[rloc * 132 + j / 3];
    }
}

// ---------------- launch ----------------
extern "C" void kernel_launch(void* const* d_in, const int* in_sizes, int n_in,
                              void* d_out, int out_size) {
    const float* node_feats = (const float*)d_in[0];
    const void*  edge_index = d_in[1];
    const float* edge_attrs = (const float*)d_in[2];
    const float* edge_feats = (const float*)d_in[3];
    const float* W_up_s     = (const float*)d_in[4];
    const float* W_up_v     = (const float*)d_in[5];
    const float* W1         = (const float*)d_in[6];
    const float* W2         = (const float*)d_in[7];
    const float* W3         = (const float*)d_in[8];
    const float* W4         = (const float*)d_in[9];
    const float* W_out_s    = (const float*)d_in[10];
    const float* W_out_v    = (const float*)d_in[11];
    float* out = (float*)d_out;

    // SILU_CST on host (same trapezoid as reference; runs at capture)
    double I = 0.0;
    for (int i = 0; i <= 200000; i++) {
        double z = -12.0 + 24.0 * ((double)i / 200000.0);
        double pdf = exp(-0.5 * z * z) * 0.3989422804014326779399461;
        double s = z / (1.0 + exp(-z));
        double f = s * s * pdf;
        I += (i == 0 || i == 200000) ? 0.5 * f : f;
    }
    I *= 24.0 / 200000.0;
    float cstF = (float)(1.0 / sqrt(I));

    cudaFuncSetAttribute(mlp_outs_fused, cudaFuncAttributeMaxDynamicSharedMemorySize, FUSE_SMEM);
    cudaFuncSetAttribute(mma_outv, cudaFuncAttributeMaxDynamicSharedMemorySize, OUTV_SMEM);

    detect_idx_kernel<<<1, 32>>>((const int*)edge_index);
    prep_all<<<dim3(128, 5), 256>>>(W2, W3, W4, W_out_s, W_out_v);
    node_up<<<dim3(157, 2, 4), 256>>>(node_feats, W_up_s, W_up_v);
    mlp_outs_fused<<<1563, 256, FUSE_SMEM>>>(edge_feats, W1, edge_index, edge_attrs,
                                             out, cstF);
    mma_outv<<<4688, 256, OUTV_SMEM>>>(edge_index, edge_attrs, out);
    (void)in_sizes; (void)n_in; (void)out_size;
}

// round 16
// speedup vs baseline: 1.0869x; 1.0869x over previous
#include <cuda_runtime.h>
#include <cuda_bf16.h>
#include <cuda_fp16.h>
#include <math.h>
#include <stdint.h>

#define NE 200000
#define NN 10000
typedef unsigned short ushort_t;

// ---------------- scratch ----------------
__device__ float gS[NN * 128];
__device__ float gV[NN * 384];                       // [n][m][u]
__device__ ushort_t gTH[(size_t)NE * 512];           // tpw fp16; only cols 256..511 used
__device__ ushort_t gW2H[64 * 64],  gW2L[64 * 64];
__device__ ushort_t gW3H[64 * 64],  gW3L[64 * 64];
__device__ ushort_t gW4H[512 * 64], gW4L[512 * 64];
__device__ ushort_t gWsH[128 * 256];
__device__ ushort_t gWvH[128 * 256];
__device__ int gIdx64;

// ---------------- helpers ----------------
__device__ __forceinline__ uint32_t smem_u32(const void* p) {
    uint32_t a;
    asm("{ .reg .u64 t; cvta.to.shared.u64 t, %1; cvt.u32.u64 %0, t; }" : "=r"(a) : "l"(p));
    return a;
}
__device__ __forceinline__ void split_bf(float x, ushort_t& h, ushort_t& l) {
    __nv_bfloat16 hb = __float2bfloat16_rn(x);
    float r = x - __bfloat162float(hb);
    __nv_bfloat16 lb = __float2bfloat16_rn(r);
    h = *(ushort_t*)&hb; l = *(ushort_t*)&lb;
}
__device__ __forceinline__ ushort_t fp16q(float x) {
    __half hb = __float2half_rn(x);
    return *(ushort_t*)&hb;
}
__device__ __forceinline__ float fp2f(ushort_t u) {
    __half b = *(__half*)&u;
    return __half2float(b);
}
__device__ __forceinline__ void mma_bf16(float c[4], const unsigned a[4], const unsigned b[2]) {
    asm volatile("mma.sync.aligned.m16n8k16.row.col.f32.bf16.bf16.f32 "
        "{%0,%1,%2,%3}, {%4,%5,%6,%7}, {%8,%9}, {%0,%1,%2,%3};\n"
        : "+f"(c[0]), "+f"(c[1]), "+f"(c[2]), "+f"(c[3])
        : "r"(a[0]), "r"(a[1]), "r"(a[2]), "r"(a[3]), "r"(b[0]), "r"(b[1]));
}
__device__ __forceinline__ void mma_f16(float c[4], const unsigned a[4], const unsigned b[2]) {
    asm volatile("mma.sync.aligned.m16n8k16.row.col.f32.f16.f16.f32 "
        "{%0,%1,%2,%3}, {%4,%5,%6,%7}, {%8,%9}, {%0,%1,%2,%3};\n"
        : "+f"(c[0]), "+f"(c[1]), "+f"(c[2]), "+f"(c[3])
        : "r"(a[0]), "r"(a[1]), "r"(a[2]), "r"(a[3]), "r"(b[0]), "r"(b[1]));
}
__device__ __forceinline__ void ldsm4(unsigned r[4], uint32_t addr) {
    asm volatile("ldmatrix.sync.aligned.m8n8.x4.shared.b16 {%0,%1,%2,%3}, [%4];"
        : "=r"(r[0]), "=r"(r[1]), "=r"(r[2]), "=r"(r[3]) : "r"(addr));
}

// ---------------- merged weight prep ----------------
__global__ void prep_all(const float* __restrict__ W2, const float* __restrict__ W3,
                         const float* __restrict__ W4, const float* __restrict__ Ws,
                         const float* __restrict__ Wv) {
    int y = blockIdx.y;
    const float* W; ushort_t *Th, *Tl; int Kd, Nd, f16;
    switch (y) {
        case 0:  W = W2; Th = gW2H; Tl = gW2L; Kd = 64;  Nd = 64;  f16 = 0; break;
        case 1:  W = W3; Th = gW3H; Tl = gW3L; Kd = 64;  Nd = 64;  f16 = 0; break;
        case 2:  W = W4; Th = gW4H; Tl = gW4L; Kd = 64;  Nd = 512; f16 = 0; break;
        case 3:  W = Ws; Th = gWsH; Tl = nullptr; Kd = 256; Nd = 128; f16 = 1; break;
        default: W = Wv; Th = gWvH; Tl = nullptr; Kd = 256; Nd = 128; f16 = 1; break;
    }
    int idx = blockIdx.x * 256 + threadIdx.x;
    if (idx >= Kd * Nd) return;
    int n = idx / Kd, k = idx - n * Kd;
    float x = W[(size_t)k * Nd + n];
    if (f16) {
        Th[(size_t)n * Kd + k] = fp16q(x);
    } else {
        ushort_t h, l; split_bf(x, h, l);
        Th[(size_t)n * Kd + k] = h;
        Tl[(size_t)n * Kd + k] = l;
    }
}

// ---------------- idx dtype detector ----------------
__global__ void detect_idx_kernel(const int* __restrict__ idx32) {
    if (threadIdx.x == 0) {
        int any = 0;
        for (int i = 1; i < 256; i += 2) any |= (idx32[i] != 0);
        gIdx64 = (any == 0) ? 1 : 0;
    }
}

// ---------------- merged node up-projections (blockIdx.z selects) --------------
__global__ void node_up(const float* __restrict__ NF,
                        const float* __restrict__ Wus, const float* __restrict__ Wuv) {
    const int BM = 64, BN = 64, BK = 16;
    __shared__ unsigned long long As2[BK][BM];
    __shared__ __align__(16) float Bs[BK][BN];
    int z = blockIdx.z;
    int veca = (z == 0);
    int offA = veca ? 0 : 128 + (z - 1);
    const float* B = veca ? Wus : Wuv;
    float* Cp = veca ? gS : gV;
    int ldc = veca ? 128 : 384;
    int offC = veca ? 0 : (z - 1) * 128;
    const float scale = 0.08838834764831845f;

    int tid = threadIdx.x;
    int tx = tid & 15, ty = tid >> 4;
    int row0 = blockIdx.x * BM, col0 = blockIdx.y * BN;
    unsigned long long acc[4][2];
#pragma unroll
    for (int i = 0; i < 4; i++) { acc[i][0] = 0ull; acc[i][1] = 0ull; }
    int la_m = tid >> 2, la_k = (tid & 3) * 4;
    int lb_k = tid >> 4, lb_n = (tid & 15) * 4;
    for (int kt = 0; kt < 128; kt += BK) {
        float a0 = 0.f, a1 = 0.f, a2 = 0.f, a3 = 0.f;
        int r = row0 + la_m;
        if (r < NN) {
            if (veca) {
                float4 v4 = *(const float4*)(NF + (size_t)r * 512 + kt + la_k);
                a0 = v4.x; a1 = v4.y; a2 = v4.z; a3 = v4.w;
            } else {
                const float* p = NF + (size_t)r * 512 + offA + (size_t)(kt + la_k) * 3;
                a0 = p[0]; a1 = p[3]; a2 = p[6]; a3 = p[9];
            }
        }
        {
            unsigned long long t;
            unsigned u0 = __float_as_uint(a0);
            asm("mov.b64 %0, {%1, %1};" : "=l"(t) : "r"(u0)); As2[la_k + 0][la_m] = t;
            unsigned u1 = __float_as_uint(a1);
            asm("mov.b64 %0, {%1, %1};" : "=l"(t) : "r"(u1)); As2[la_k + 1][la_m] = t;
            unsigned u2 = __float_as_uint(a2);
            asm("mov.b64 %0, {%1, %1};" : "=l"(t) : "r"(u2)); As2[la_k + 2][la_m] = t;
            unsigned u3 = __float_as_uint(a3);
            asm("mov.b64 %0, {%1, %1};" : "=l"(t) : "r"(u3)); As2[la_k + 3][la_m] = t;
        }
        *(float4*)&Bs[lb_k][lb_n] = *(const float4*)(B + (size_t)(kt + lb_k) * 128 + col0 + lb_n);
        __syncthreads();
#pragma unroll
        for (int kk = 0; kk < BK; kk++) {
            ulonglong2 b01 = *(const ulonglong2*)&Bs[kk][tx * 4];
            unsigned long long av[4];
#pragma unroll
            for (int i = 0; i < 4; i++) av[i] = As2[kk][ty * 4 + i];
#pragma unroll
            for (int i = 0; i < 4; i++) {
                asm("fma.rn.f32x2 %0, %1, %2, %0;" : "+l"(acc[i][0]) : "l"(av[i]), "l"(b01.x));
                asm("fma.rn.f32x2 %0, %1, %2, %0;" : "+l"(acc[i][1]) : "l"(av[i]), "l"(b01.y));
            }
        }
        __syncthreads();
    }
#pragma unroll
    for (int i = 0; i < 4; i++) {
        int r = row0 + ty * 4 + i;
        if (r >= NN) continue;
#pragma unroll
        for (int jp = 0; jp < 2; jp++) {
            unsigned lo, hi;
            asm("mov.b64 {%0, %1}, %2;" : "=r"(lo), "=r"(hi) : "l"(acc[i][jp]));
            int c0 = col0 + tx * 4 + jp * 2;
            Cp[(size_t)r * ldc + offC + c0]     = __uint_as_float(lo) * scale;
            Cp[(size_t)r * ldc + offC + c0 + 1] = __uint_as_float(hi) * scale;
        }
    }
}

// ---------------- fused MLP + W4 + out_s; 64-row tiles, 128 threads, 2 CTA/SM --
// smem: sEF @0 (2048) | sW1 @2048 (2048) | Ah @4096 | Al @13312 | Ao @22528
//       | Bw @31744 (18432) | sSnd @50176 (256) | sY @50432 (1024) = 51456
#define FUSE_SMEM 51456
__global__ __launch_bounds__(128, 2) void mlp_outs_fused(
        const float* __restrict__ EF, const float* __restrict__ W1,
        const void* __restrict__ eidx, const float* __restrict__ eattr,
        float* __restrict__ C, float cstv) {
    const int PK = 72;
    const int RB = PK * 2;
    extern __shared__ __align__(16) char sm[];
    float* sEF = (float*)sm;
    float* sW1 = (float*)(sm + 2048);
    ushort_t (*Ah)[PK] = (ushort_t(*)[PK])(sm + 4096);
    ushort_t (*Al)[PK] = (ushort_t(*)[PK])(sm + 13312);
    ushort_t (*Ao)[PK] = (ushort_t(*)[PK])(sm + 22528);
    ushort_t (*Bw)[PK] = (ushort_t(*)[PK])(sm + 31744);
    int*    sSnd = (int*)(sm + 50176);
    float4* sY   = (float4*)(sm + 50432);

    int tid = threadIdx.x, wid = tid >> 5, lane = tid & 31;
    int warp_m = wid & 1, warp_n = wid >> 1;          // 2x2 warps, 64x64 tile
    int g = lane >> 2, tg = lane & 3;
    int row0 = blockIdx.x * 64;
    int am = warp_m * 32, bn = warp_n * 32;

    {
        int r = tid >> 1, hf = tid & 1;               // r 0..63
        int e = min(row0 + r, NE - 1);
        *(float4*)&sEF[r * 8 + hf * 4] = *(const float4*)(EF + (size_t)e * 8 + hf * 4);
        *(float4*)&sW1[tid * 4] = *(const float4*)(W1 + tid * 4);
        if (tid < 64) {
            int ee = min(row0 + tid, NE - 1);
            int snd = gIdx64 ? (int)((const long long*)eidx)[ee] : ((const int*)eidx)[ee];
            sSnd[tid] = min(max(snd, 0), NN - 1);
            sY[tid] = *(const float4*)(eattr + 4 * ee);
        }
    }
    __syncthreads();

    // H1 = silu(ef @ W1 * inv8) * cst  -> Ah/Al
    {
        int r = tid >> 1, hf = tid & 1;
        float ef[8];
#pragma unroll
        for (int k = 0; k < 8; k++) ef[k] = sEF[r * 8 + k];
#pragma unroll
        for (int c0 = 0; c0 < 32; c0 += 2) {
            int c = hf * 32 + c0;
            float x0 = 0.f, x1 = 0.f;
#pragma unroll
            for (int k = 0; k < 8; k++) {
                x0 += ef[k] * sW1[k * 64 + c];
                x1 += ef[k] * sW1[k * 64 + c + 1];
            }
            x0 *= 0.35355339059327373f; x1 *= 0.35355339059327373f;
            x0 = x0 / (1.f + __expf(-x0)) * cstv;
            x1 = x1 / (1.f + __expf(-x1)) * cstv;
            ushort_t h0, l0, h1, l1;
            split_bf(x0, h0, l0); split_bf(x1, h1, l1);
            ushort2 ph; ph.x = h0; ph.y = h1;
            ushort2 pl; pl.x = l0; pl.y = l1;
            *(ushort2*)&Ah[r][c] = ph;
            *(ushort2*)&Al[r][c] = pl;
        }
    }

    int arow = (lane & 7) + ((lane >> 3) & 1) * 8;
    int acol = (lane >> 4) * 8;
    uint32_t aH = smem_u32(&Ah[am + arow][acol]);
    uint32_t aL = smem_u32(&Al[am + arow][acol]);
    uint32_t aO = smem_u32(&Ao[am + arow][acol]);
    int brow = (lane & 7) + ((lane >> 4) & 1) * 8;
    int bcol = ((lane >> 3) & 1) * 8;
    uint32_t bH = smem_u32(&Bw[bn + brow][bcol]);
    uint32_t bL = bH + 64 * RB;

    float acc[2][4][4];
    float acco[2][2][4][4];
#pragma unroll
    for (int n2 = 0; n2 < 2; n2++)
#pragma unroll
        for (int mt = 0; mt < 2; mt++)
#pragma unroll
            for (int nt = 0; nt < 4; nt++)
#pragma unroll
                for (int j = 0; j < 4; j++) acco[n2][mt][nt][j] = 0.f;

    auto zacc = [&] {
#pragma unroll
        for (int mt = 0; mt < 2; mt++)
#pragma unroll
            for (int nt = 0; nt < 4; nt++)
#pragma unroll
                for (int j = 0; j < 4; j++) acc[mt][nt][j] = 0.f;
    };
    auto stageB = [&](const ushort_t* TH, const ushort_t* TL, int n0) {
#pragma unroll
        for (int i = 0; i < 4; i++) {
            int idx = tid + i * 128;
            int r = idx >> 3, c8 = (idx & 7) * 8;      // r 0..63
            *(uint4*)&Bw[r][c8] = *(const uint4*)(TH + (size_t)(n0 + r) * 64 + c8);
            *(uint4*)&Bw[r + 64][c8] = *(const uint4*)(TL + (size_t)(n0 + r) * 64 + c8);
        }
    };
    auto mmaAB = [&] {
#pragma unroll
        for (int ks = 0; ks < 4; ks++) {
            unsigned ah[2][4], al[2][4], bh[2][4], bl[2][4];
#pragma unroll
            for (int mt = 0; mt < 2; mt++) {
                ldsm4(ah[mt], aH + mt * (16 * RB) + ks * 32);
                ldsm4(al[mt], aL + mt * (16 * RB) + ks * 32);
            }
#pragma unroll
            for (int np = 0; np < 2; np++) {
                ldsm4(bh[np], bH + np * (16 * RB) + ks * 32);
                ldsm4(bl[np], bL + np * (16 * RB) + ks * 32);
            }
#pragma unroll
            for (int mt = 0; mt < 2; mt++)
#pragma unroll
                for (int nt = 0; nt < 4; nt++)
                    mma_bf16(acc[mt][nt], ah[mt], &bh[nt >> 1][(nt & 1) * 2]);
#pragma unroll
            for (int mt = 0; mt < 2; mt++)
#pragma unroll
                for (int nt = 0; nt < 4; nt++)
                    mma_bf16(acc[mt][nt], ah[mt], &bl[nt >> 1][(nt & 1) * 2]);
#pragma unroll
            for (int mt = 0; mt < 2; mt++)
#pragma unroll
                for (int nt = 0; nt < 4; nt++)
                    mma_bf16(acc[mt][nt], al[mt], &bh[nt >> 1][(nt & 1) * 2]);
        }
    };
    auto epiH = [&](float scale) {
#pragma unroll
        for (int mt = 0; mt < 2; mt++) {
            int r1 = am + mt * 16 + g, r2 = r1 + 8;
#pragma unroll
            for (int nt = 0; nt < 4; nt++) {
                int cc = bn + nt * 8 + tg * 2;
                float xs[4];
#pragma unroll
                for (int j = 0; j < 4; j++) {
                    float x = acc[mt][nt][j] * scale;
                    xs[j] = x / (1.f + __expf(-x)) * cstv;
                }
                ushort_t h0, l0, h1, l1;
                split_bf(xs[0], h0, l0); split_bf(xs[1], h1, l1);
                ushort2 ph; ph.x = h0; ph.y = h1;
                ushort2 pl; pl.x = l0; pl.y = l1;
                *(ushort2*)&Ah[r1][cc] = ph; *(ushort2*)&Al[r1][cc] = pl;
                split_bf(xs[2], h0, l0); split_bf(xs[3], h1, l1);
                ph.x = h0; ph.y = h1; pl.x = l0; pl.y = l1;
                *(ushort2*)&Ah[r2][cc] = ph; *(ushort2*)&Al[r2][cc] = pl;
            }
        }
    };

    const float inv64 = 0.125f;
    stageB(gW2H, gW2L, 0);
    __syncthreads();
    zacc(); mmaAB();
    __syncthreads();
    epiH(inv64);
    stageB(gW3H, gW3L, 0);
    __syncthreads();
    zacc(); mmaAB();
    __syncthreads();
    epiH(inv64);
    __syncthreads();

    for (int n0 = 0; n0 < 512; n0 += 64) {
        stageB(gW4H, gW4L, n0);
        __syncthreads();
        zacc(); mmaAB();

        if (n0 < 256) {
            __syncthreads();
            // multiply T-chunk accumulators by gather factor -> Ao (fp16)
#pragma unroll
            for (int mt = 0; mt < 2; mt++) {
#pragma unroll
                for (int hrow = 0; hrow < 2; hrow++) {
                    int rloc = am + mt * 16 + g + hrow * 8;
                    int snd = sSnd[rloc];
                    float4 y = sY[rloc];
#pragma unroll
                    for (int nt = 0; nt < 4; nt++) {
                        int cc = bn + nt * 8 + tg * 2;
                        int k = n0 + cc;
                        float f0, f1;
                        if (n0 < 128) {
                            const float* sp = gS + (size_t)snd * 128 + k;
                            f0 = sp[0] * y.x; f1 = sp[1] * y.x;
                        } else {
                            int u = k - 128;
                            const float* vp = gV + (size_t)snd * 384 + u;
                            f0 = (vp[0] * y.y + vp[128] * y.z + vp[256] * y.w) * 0.57735026918962576f;
                            f1 = (vp[1] * y.y + vp[129] * y.z + vp[257] * y.w) * 0.57735026918962576f;
                        }
                        float a0 = acc[mt][nt][2 * hrow + 0] * inv64 * f0;
                        float a1 = acc[mt][nt][2 * hrow + 1] * inv64 * f1;
                        ushort2 p; p.x = fp16q(a0); p.y = fp16q(a1);
                        *(ushort2*)&Ao[rloc][cc] = p;
                    }
                }
            }
            // stage Ws chunk [128 N][64 K] -> Bw rows 0..127
#pragma unroll
            for (int i = 0; i < 8; i++) {
                int idx = tid + i * 128;
                int r = idx >> 3, c8 = (idx & 7) * 8;
                *(uint4*)&Bw[r][c8] = *(const uint4*)(gWsH + (size_t)r * 256 + n0 + c8);
            }
            __syncthreads();
#pragma unroll
            for (int ks = 0; ks < 4; ks++) {
                unsigned ah[2][4];
#pragma unroll
                for (int mt = 0; mt < 2; mt++)
                    ldsm4(ah[mt], aO + mt * (16 * RB) + ks * 32);
#pragma unroll
                for (int n2 = 0; n2 < 2; n2++) {
                    unsigned bh[2][4];
#pragma unroll
                    for (int np = 0; np < 2; np++)
                        ldsm4(bh[np], bH + n2 * (64 * RB) + np * (16 * RB) + ks * 32);
#pragma unroll
                    for (int mt = 0; mt < 2; mt++)
#pragma unroll
                        for (int nt = 0; nt < 4; nt++)
                            mma_f16(acco[n2][mt][nt], ah[mt], &bh[nt >> 1][(nt & 1) * 2]);
                }
            }
            __syncthreads();
        } else {
#pragma unroll
            for (int mt = 0; mt < 2; mt++) {
                int r1 = row0 + am + mt * 16 + g, r2 = r1 + 8;
#pragma unroll
                for (int nt = 0; nt < 4; nt++) {
                    int cc = bn + nt * 8 + tg * 2;
                    if (r1 < NE) {
                        ushort2 p; p.x = fp16q(acc[mt][nt][0] * inv64);
                        p.y = fp16q(acc[mt][nt][1] * inv64);
                        *(ushort2*)&gTH[(size_t)r1 * 512 + n0 + cc] = p;
                    }
                    if (r2 < NE) {
                        ushort2 p; p.x = fp16q(acc[mt][nt][2] * inv64);
                        p.y = fp16q(acc[mt][nt][3] * inv64);
                        *(ushort2*)&gTH[(size_t)r2 * 512 + n0 + cc] = p;
                    }
                }
            }
            __syncthreads();
        }
    }

    // ---- out_s epilogue: C[:, :128] ----
#pragma unroll
    for (int n2 = 0; n2 < 2; n2++) {
#pragma unroll
        for (int mt = 0; mt < 2; mt++) {
            int rr[2]; rr[0] = row0 + am + mt * 16 + g; rr[1] = rr[0] + 8;
#pragma unroll
            for (int nt = 0; nt < 4; nt++) {
                int cc = n2 * 64 + bn + nt * 8 + tg * 2;
#pragma unroll
                for (int h = 0; h < 2; h++) {
                    int gr = rr[h];
                    if (gr >= NE) continue;
                    float x0 = acco[n2][mt][nt][2 * h] * 0.0625f;
                    float x1 = acco[n2][mt][nt][2 * h + 1] * 0.0625f;
                    *(float2*)&C[(size_t)gr * 512 + cc] = make_float2(x0, x1);
                }
            }
        }
    }
}

// ---------------- fused out_v (R14 version: direct scatter epilogue) -----------
__global__ __launch_bounds__(256, 2) void mma_outv(
        const void* __restrict__ eidx, const float* __restrict__ eattr,
        float* __restrict__ C) {
    const int PK = 40;
    __shared__ __align__(16) ushort_t Ah[128][PK];
    __shared__ __align__(16) ushort_t Bhs[128][PK];
    __shared__ int sSnd[128];
    __shared__ float sY0[128], sYm[128];

    int tid = threadIdx.x;
    int wid = tid >> 5, lane = tid & 31;
    int warp_m = wid & 3, warp_n = wid >> 2;
    int g = lane >> 2, tg = lane & 3;
    int row0 = blockIdx.x * 128;
    int am = warp_m * 32, bn = warp_n * 32;

    if (tid < 128) {
        int gr = min(row0 + tid, 3 * NE - 1);
        int e = gr / 3, m = gr - 3 * e;
        int snd = gIdx64 ? (int)((const long long*)eidx)[e] : ((const int*)eidx)[e];
        sSnd[tid] = min(max(snd, 0), NN - 1);
        float4 y = *(const float4*)(eattr + 4 * e);
        sY0[tid] = y.x;
        sYm[tid] = (m == 0) ? y.y : ((m == 1) ? y.z : y.w);
    }
    __syncthreads();

    int arow = (lane & 7) + ((lane >> 3) & 1) * 8;
    int acol = (lane >> 4) * 8;
    uint32_t aH = smem_u32(&Ah[am + arow][acol]);
    int brow = (lane & 7) + ((lane >> 4) & 1) * 8;
    int bcol = ((lane >> 3) & 1) * 8;
    uint32_t bH = smem_u32(&Bhs[bn + brow][bcol]);

    float acc[2][2][4][4];
#pragma unroll
    for (int n2 = 0; n2 < 2; n2++)
#pragma unroll
        for (int mt = 0; mt < 2; mt++)
#pragma unroll
            for (int nt = 0; nt < 4; nt++)
#pragma unroll
                for (int j = 0; j < 4; j++) acc[n2][mt][nt][j] = 0.f;

    int r = tid >> 1, half = tid & 1;
    int grr = min(row0 + r, 3 * NE - 1);
    int e = grr / 3, m = grr - 3 * e;
    int snd = sSnd[r];
    float y0 = sY0[r], ym = sYm[r];

    auto computeA = [&](int kc, ushort_t* hh) {
        int u0 = (kc & 3) * 32 + half * 16;
        size_t tb = (size_t)e * 512 + (kc < 4 ? 256 : 384) + u0;
        __align__(16) ushort_t th[16];
        *(uint4*)&th[0] = *(const uint4*)(gTH + tb);
        *(uint4*)&th[8] = *(const uint4*)(gTH + tb + 8);
        if (kc < 4) {
            const float* sp = gS + (size_t)snd * 128 + u0;
#pragma unroll
            for (int j = 0; j < 16; j++)
                hh[j] = fp16q(fp2f(th[j]) * sp[j] * ym);
        } else {
            const float* vp = gV + (size_t)snd * 384 + m * 128 + u0;
#pragma unroll
            for (int j = 0; j < 16; j++)
                hh[j] = fp16q(fp2f(th[j]) * y0 * vp[j]);
        }
    };

    __align__(16) ushort_t hc[16], hn[16];
    computeA(0, hc);

    for (int kc = 0; kc < 8; kc++) {
        *(uint4*)&Ah[r][half * 16] = *(uint4*)&hc[0];
        *(uint4*)&Ah[r][half * 16 + 8] = *(uint4*)&hc[8];
        {
            const ushort_t* ph = gWvH + (size_t)r * 256 + kc * 32 + half * 16;
            *(uint4*)&Bhs[r][half * 16] = *(const uint4*)ph;
            *(uint4*)&Bhs[r][half * 16 + 8] = *(const uint4*)(ph + 8);
        }
        __syncthreads();
        if (kc < 7) computeA(kc + 1, hn);

#pragma unroll
        for (int ks = 0; ks < 2; ks++) {
            unsigned ah[2][4];
#pragma unroll
            for (int mt = 0; mt < 2; mt++)
                ldsm4(ah[mt], aH + mt * (16 * PK * 2) + ks * 32);
#pragma unroll
            for (int n2 = 0; n2 < 2; n2++) {
                unsigned bh[2][4];
#pragma unroll
                for (int np = 0; np < 2; np++)
                    ldsm4(bh[np], bH + n2 * (64 * PK * 2) + np * (16 * PK * 2) + ks * 32);
#pragma unroll
                for (int mt = 0; mt < 2; mt++)
#pragma unroll
                    for (int nt = 0; nt < 4; nt++)
                        mma_f16(acc[n2][mt][nt], ah[mt], &bh[nt >> 1][(nt & 1) * 2]);
            }
        }
        __syncthreads();
#pragma unroll
        for (int j = 0; j < 16; j++) hc[j] = hn[j];
    }

#pragma unroll
    for (int n2 = 0; n2 < 2; n2++) {
#pragma unroll
        for (int mt = 0; mt < 2; mt++) {
            int rr[2]; rr[0] = row0 + am + mt * 16 + g; rr[1] = rr[0] + 8;
#pragma unroll
            for (int nt = 0; nt < 4; nt++) {
                int cc = n2 * 64 + bn + nt * 8 + tg * 2;
#pragma unroll
                for (int h = 0; h < 2; h++) {
                    int gr = rr[h];
                    if (gr >= 3 * NE) continue;
                    int ee = gr / 3, mm = gr - 3 * ee;
                    float x0 = acc[n2][mt][nt][2 * h] * 0.0625f;
                    float x1 = acc[n2][mt][nt][2 * h + 1] * 0.0625f;
                    C[(size_t)ee * 512 + 128 + mm + 3 * cc] = x0;
                    C[(size_t)ee * 512 + 128 + mm + 3 * (cc + 1)] = x1;
                }
            }
        }
    }
}

// ---------------- launch ----------------
extern "C" void kernel_launch(void* const* d_in, const int* in_sizes, int n_in,
                              void* d_out, int out_size) {
    const float* node_feats = (const float*)d_in[0];
    const void*  edge_index = d_in[1];
    const float* edge_attrs = (const float*)d_in[2];
    const float* edge_feats = (const float*)d_in[3];
    const float* W_up_s     = (const float*)d_in[4];
    const float* W_up_v     = (const float*)d_in[5];
    const float* W1         = (const float*)d_in[6];
    const float* W2         = (const float*)d_in[7];
    const float* W3         = (const float*)d_in[8];
    const float* W4         = (const float*)d_in[9];
    const float* W_out_s    = (const float*)d_in[10];
    const float* W_out_v    = (const float*)d_in[11];
    float* out = (float*)d_out;

    // SILU_CST on host (same trapezoid as reference; runs at capture)
    double I = 0.0;
    for (int i = 0; i <= 200000; i++) {
        double z = -12.0 + 24.0 * ((double)i / 200000.0);
        double pdf = exp(-0.5 * z * z) * 0.3989422804014326779399461;
        double s = z / (1.0 + exp(-z));
        double f = s * s * pdf;
        I += (i == 0 || i == 200000) ? 0.5 * f : f;
    }
    I *= 24.0 / 200000.0;
    float cstF = (float)(1.0 / sqrt(I));

    cudaFuncSetAttribute(mlp_outs_fused, cudaFuncAttributeMaxDynamicSharedMemorySize, FUSE_SMEM);

    detect_idx_kernel<<<1, 32>>>((const int*)edge_index);
    prep_all<<<dim3(128, 5), 256>>>(W2, W3, W4, W_out_s, W_out_v);
    node_up<<<dim3(157, 2, 4), 256>>>(node_feats, W_up_s, W_up_v);
    mlp_outs_fused<<<3125, 128, FUSE_SMEM>>>(edge_feats, W1, edge_index, edge_attrs,
                                             out, cstF);
    mma_outv<<<4688, 256>>>(edge_index, edge_attrs, out);
    (void)in_sizes; (void)n_in; (void)out_size;
}

// round 17
// speedup vs baseline: 1.1213x; 1.0316x over previous
#include <cuda_runtime.h>
#include <cuda_bf16.h>
#include <cuda_fp16.h>
#include <math.h>
#include <stdint.h>

#define NE 200000
#define NN 10000
typedef unsigned short ushort_t;

// ---------------- scratch ----------------
__device__ float gS[NN * 128];
__device__ float gV[NN * 384];                       // [n][m][u]
__device__ ushort_t gTH[(size_t)NE * 512];           // tpw fp16; only cols 256..511 used
// MLP weights: fp16 hi/lo planes [N][K]
__device__ ushort_t gW2H[64 * 64],  gW2L[64 * 64];
__device__ ushort_t gW3H[64 * 64],  gW3L[64 * 64];
__device__ ushort_t gW4H[512 * 64], gW4L[512 * 64];
// output weights: fp16 hi only [N][K]
__device__ ushort_t gWsH[128 * 256];
__device__ ushort_t gWvH[128 * 256];
__device__ int gIdx64;

// ---------------- helpers ----------------
__device__ __forceinline__ uint32_t smem_u32(const void* p) {
    uint32_t a;
    asm("{ .reg .u64 t; cvta.to.shared.u64 t, %1; cvt.u32.u64 %0, t; }" : "=r"(a) : "l"(p));
    return a;
}
__device__ __forceinline__ void split_fp16(float x, ushort_t& h, ushort_t& l) {
    __half hb = __float2half_rn(x);
    float r = x - __half2float(hb);
    __half lb = __float2half_rn(r);
    h = *(ushort_t*)&hb; l = *(ushort_t*)&lb;
}
__device__ __forceinline__ ushort_t fp16q(float x) {
    __half hb = __float2half_rn(x);
    return *(ushort_t*)&hb;
}
__device__ __forceinline__ float fp2f(ushort_t u) {
    __half b = *(__half*)&u;
    return __half2float(b);
}
__device__ __forceinline__ void mma_f16(float c[4], const unsigned a[4], const unsigned b[2]) {
    asm volatile("mma.sync.aligned.m16n8k16.row.col.f32.f16.f16.f32 "
        "{%0,%1,%2,%3}, {%4,%5,%6,%7}, {%8,%9}, {%0,%1,%2,%3};\n"
        : "+f"(c[0]), "+f"(c[1]), "+f"(c[2]), "+f"(c[3])
        : "r"(a[0]), "r"(a[1]), "r"(a[2]), "r"(a[3]), "r"(b[0]), "r"(b[1]));
}
__device__ __forceinline__ void ldsm4(unsigned r[4], uint32_t addr) {
    asm volatile("ldmatrix.sync.aligned.m8n8.x4.shared.b16 {%0,%1,%2,%3}, [%4];"
        : "=r"(r[0]), "=r"(r[1]), "=r"(r[2]), "=r"(r[3]) : "r"(addr));
}

// ---------------- merged weight prep ----------------
__global__ void prep_all(const float* __restrict__ W2, const float* __restrict__ W3,
                         const float* __restrict__ W4, const float* __restrict__ Ws,
                         const float* __restrict__ Wv) {
    int y = blockIdx.y;
    const float* W; ushort_t *Th, *Tl; int Kd, Nd, hionly;
    switch (y) {
        case 0:  W = W2; Th = gW2H; Tl = gW2L; Kd = 64;  Nd = 64;  hionly = 0; break;
        case 1:  W = W3; Th = gW3H; Tl = gW3L; Kd = 64;  Nd = 64;  hionly = 0; break;
        case 2:  W = W4; Th = gW4H; Tl = gW4L; Kd = 64;  Nd = 512; hionly = 0; break;
        case 3:  W = Ws; Th = gWsH; Tl = nullptr; Kd = 256; Nd = 128; hionly = 1; break;
        default: W = Wv; Th = gWvH; Tl = nullptr; Kd = 256; Nd = 128; hionly = 1; break;
    }
    int idx = blockIdx.x * 256 + threadIdx.x;
    if (idx >= Kd * Nd) return;
    int n = idx / Kd, k = idx - n * Kd;
    float x = W[(size_t)k * Nd + n];
    if (hionly) {
        Th[(size_t)n * Kd + k] = fp16q(x);
    } else {
        ushort_t h, l; split_fp16(x, h, l);
        Th[(size_t)n * Kd + k] = h;
        Tl[(size_t)n * Kd + k] = l;
    }
}

// ---------------- idx dtype detector ----------------
__global__ void detect_idx_kernel(const int* __restrict__ idx32) {
    if (threadIdx.x == 0) {
        int any = 0;
        for (int i = 1; i < 256; i += 2) any |= (idx32[i] != 0);
        gIdx64 = (any == 0) ? 1 : 0;
    }
}

// ---------------- merged node up-projections (blockIdx.z selects) --------------
__global__ void node_up(const float* __restrict__ NF,
                        const float* __restrict__ Wus, const float* __restrict__ Wuv) {
    const int BM = 64, BN = 64, BK = 16;
    __shared__ unsigned long long As2[BK][BM];
    __shared__ __align__(16) float Bs[BK][BN];
    int z = blockIdx.z;
    int veca = (z == 0);
    int offA = veca ? 0 : 128 + (z - 1);
    const float* B = veca ? Wus : Wuv;
    float* Cp = veca ? gS : gV;
    int ldc = veca ? 128 : 384;
    int offC = veca ? 0 : (z - 1) * 128;
    const float scale = 0.08838834764831845f;

    int tid = threadIdx.x;
    int tx = tid & 15, ty = tid >> 4;
    int row0 = blockIdx.x * BM, col0 = blockIdx.y * BN;
    unsigned long long acc[4][2];
#pragma unroll
    for (int i = 0; i < 4; i++) { acc[i][0] = 0ull; acc[i][1] = 0ull; }
    int la_m = tid >> 2, la_k = (tid & 3) * 4;
    int lb_k = tid >> 4, lb_n = (tid & 15) * 4;
    for (int kt = 0; kt < 128; kt += BK) {
        float a0 = 0.f, a1 = 0.f, a2 = 0.f, a3 = 0.f;
        int r = row0 + la_m;
        if (r < NN) {
            if (veca) {
                float4 v4 = *(const float4*)(NF + (size_t)r * 512 + kt + la_k);
                a0 = v4.x; a1 = v4.y; a2 = v4.z; a3 = v4.w;
            } else {
                const float* p = NF + (size_t)r * 512 + offA + (size_t)(kt + la_k) * 3;
                a0 = p[0]; a1 = p[3]; a2 = p[6]; a3 = p[9];
            }
        }
        {
            unsigned long long t;
            unsigned u0 = __float_as_uint(a0);
            asm("mov.b64 %0, {%1, %1};" : "=l"(t) : "r"(u0)); As2[la_k + 0][la_m] = t;
            unsigned u1 = __float_as_uint(a1);
            asm("mov.b64 %0, {%1, %1};" : "=l"(t) : "r"(u1)); As2[la_k + 1][la_m] = t;
            unsigned u2 = __float_as_uint(a2);
            asm("mov.b64 %0, {%1, %1};" : "=l"(t) : "r"(u2)); As2[la_k + 2][la_m] = t;
            unsigned u3 = __float_as_uint(a3);
            asm("mov.b64 %0, {%1, %1};" : "=l"(t) : "r"(u3)); As2[la_k + 3][la_m] = t;
        }
        *(float4*)&Bs[lb_k][lb_n] = *(const float4*)(B + (size_t)(kt + lb_k) * 128 + col0 + lb_n);
        __syncthreads();
#pragma unroll
        for (int kk = 0; kk < BK; kk++) {
            ulonglong2 b01 = *(const ulonglong2*)&Bs[kk][tx * 4];
            unsigned long long av[4];
#pragma unroll
            for (int i = 0; i < 4; i++) av[i] = As2[kk][ty * 4 + i];
#pragma unroll
            for (int i = 0; i < 4; i++) {
                asm("fma.rn.f32x2 %0, %1, %2, %0;" : "+l"(acc[i][0]) : "l"(av[i]), "l"(b01.x));
                asm("fma.rn.f32x2 %0, %1, %2, %0;" : "+l"(acc[i][1]) : "l"(av[i]), "l"(b01.y));
            }
        }
        __syncthreads();
    }
#pragma unroll
    for (int i = 0; i < 4; i++) {
        int r = row0 + ty * 4 + i;
        if (r >= NN) continue;
#pragma unroll
        for (int jp = 0; jp < 2; jp++) {
            unsigned lo, hi;
            asm("mov.b64 {%0, %1}, %2;" : "=r"(lo), "=r"(hi) : "l"(acc[i][jp]));
            int c0 = col0 + tx * 4 + jp * 2;
            Cp[(size_t)r * ldc + offC + c0]     = __uint_as_float(lo) * scale;
            Cp[(size_t)r * ldc + offC + c0 + 1] = __uint_as_float(hi) * scale;
        }
    }
}

// ---------------- fused MLP + W4 + out_s; fp16 2-product, A single plane -------
// smem: sEF @0 (2048) | sW1 @2048 (2048) | Ah @4096 (9216) | Ao @13312 (9216)
//       | Bw @22528 (18432) | sSnd @40960 (256) | sY @41216 (1024) = 42240
#define FUSE_SMEM 42240
__global__ __launch_bounds__(128, 2) void mlp_outs_fused(
        const float* __restrict__ EF, const float* __restrict__ W1,
        const void* __restrict__ eidx, const float* __restrict__ eattr,
        float* __restrict__ C, float cstv) {
    const int PK = 72;
    const int RB = PK * 2;
    extern __shared__ __align__(16) char sm[];
    float* sEF = (float*)sm;
    float* sW1 = (float*)(sm + 2048);
    ushort_t (*Ah)[PK] = (ushort_t(*)[PK])(sm + 4096);
    ushort_t (*Ao)[PK] = (ushort_t(*)[PK])(sm + 13312);
    ushort_t (*Bw)[PK] = (ushort_t(*)[PK])(sm + 22528);
    int*    sSnd = (int*)(sm + 40960);
    float4* sY   = (float4*)(sm + 41216);

    int tid = threadIdx.x, wid = tid >> 5, lane = tid & 31;
    int warp_m = wid & 1, warp_n = wid >> 1;          // 2x2 warps, 64x64 tile
    int g = lane >> 2, tg = lane & 3;
    int row0 = blockIdx.x * 64;
    int am = warp_m * 32, bn = warp_n * 32;

    {
        int r = tid >> 1, hf = tid & 1;
        int e = min(row0 + r, NE - 1);
        *(float4*)&sEF[r * 8 + hf * 4] = *(const float4*)(EF + (size_t)e * 8 + hf * 4);
        *(float4*)&sW1[tid * 4] = *(const float4*)(W1 + tid * 4);
        if (tid < 64) {
            int ee = min(row0 + tid, NE - 1);
            int snd = gIdx64 ? (int)((const long long*)eidx)[ee] : ((const int*)eidx)[ee];
            sSnd[tid] = min(max(snd, 0), NN - 1);
            sY[tid] = *(const float4*)(eattr + 4 * ee);
        }
    }
    __syncthreads();

    // H1 = silu(ef @ W1 * inv8) * cst  -> Ah (fp16)
    {
        int r = tid >> 1, hf = tid & 1;
        float ef[8];
#pragma unroll
        for (int k = 0; k < 8; k++) ef[k] = sEF[r * 8 + k];
#pragma unroll
        for (int c0 = 0; c0 < 32; c0 += 2) {
            int c = hf * 32 + c0;
            float x0 = 0.f, x1 = 0.f;
#pragma unroll
            for (int k = 0; k < 8; k++) {
                x0 += ef[k] * sW1[k * 64 + c];
                x1 += ef[k] * sW1[k * 64 + c + 1];
            }
            x0 *= 0.35355339059327373f; x1 *= 0.35355339059327373f;
            x0 = x0 / (1.f + __expf(-x0)) * cstv;
            x1 = x1 / (1.f + __expf(-x1)) * cstv;
            ushort2 p; p.x = fp16q(x0); p.y = fp16q(x1);
            *(ushort2*)&Ah[r][c] = p;
        }
    }

    int arow = (lane & 7) + ((lane >> 3) & 1) * 8;
    int acol = (lane >> 4) * 8;
    uint32_t aH = smem_u32(&Ah[am + arow][acol]);
    uint32_t aO = smem_u32(&Ao[am + arow][acol]);
    int brow = (lane & 7) + ((lane >> 4) & 1) * 8;
    int bcol = ((lane >> 3) & 1) * 8;
    uint32_t bH = smem_u32(&Bw[bn + brow][bcol]);
    uint32_t bL = bH + 64 * RB;

    float acc[2][4][4];
    float acco[2][2][4][4];
#pragma unroll
    for (int n2 = 0; n2 < 2; n2++)
#pragma unroll
        for (int mt = 0; mt < 2; mt++)
#pragma unroll
            for (int nt = 0; nt < 4; nt++)
#pragma unroll
                for (int j = 0; j < 4; j++) acco[n2][mt][nt][j] = 0.f;

    auto zacc = [&] {
#pragma unroll
        for (int mt = 0; mt < 2; mt++)
#pragma unroll
            for (int nt = 0; nt < 4; nt++)
#pragma unroll
                for (int j = 0; j < 4; j++) acc[mt][nt][j] = 0.f;
    };
    auto stageB = [&](const ushort_t* TH, const ushort_t* TL, int n0) {
#pragma unroll
        for (int i = 0; i < 4; i++) {
            int idx = tid + i * 128;
            int r = idx >> 3, c8 = (idx & 7) * 8;
            *(uint4*)&Bw[r][c8] = *(const uint4*)(TH + (size_t)(n0 + r) * 64 + c8);
            *(uint4*)&Bw[r + 64][c8] = *(const uint4*)(TL + (size_t)(n0 + r) * 64 + c8);
        }
    };
    // fp16 2-product: A(hi) x (Bhi + Blo)
    auto mmaAB = [&] {
#pragma unroll
        for (int ks = 0; ks < 4; ks++) {
            unsigned ah[2][4], bh[2][4], bl[2][4];
#pragma unroll
            for (int mt = 0; mt < 2; mt++)
                ldsm4(ah[mt], aH + mt * (16 * RB) + ks * 32);
#pragma unroll
            for (int np = 0; np < 2; np++) {
                ldsm4(bh[np], bH + np * (16 * RB) + ks * 32);
                ldsm4(bl[np], bL + np * (16 * RB) + ks * 32);
            }
#pragma unroll
            for (int mt = 0; mt < 2; mt++)
#pragma unroll
                for (int nt = 0; nt < 4; nt++)
                    mma_f16(acc[mt][nt], ah[mt], &bh[nt >> 1][(nt & 1) * 2]);
#pragma unroll
            for (int mt = 0; mt < 2; mt++)
#pragma unroll
                for (int nt = 0; nt < 4; nt++)
                    mma_f16(acc[mt][nt], ah[mt], &bl[nt >> 1][(nt & 1) * 2]);
        }
    };
    auto epiH = [&](float scale) {
#pragma unroll
        for (int mt = 0; mt < 2; mt++) {
            int r1 = am + mt * 16 + g, r2 = r1 + 8;
#pragma unroll
            for (int nt = 0; nt < 4; nt++) {
                int cc = bn + nt * 8 + tg * 2;
                float xs[4];
#pragma unroll
                for (int j = 0; j < 4; j++) {
                    float x = acc[mt][nt][j] * scale;
                    xs[j] = x / (1.f + __expf(-x)) * cstv;
                }
                ushort2 p;
                p.x = fp16q(xs[0]); p.y = fp16q(xs[1]);
                *(ushort2*)&Ah[r1][cc] = p;
                p.x = fp16q(xs[2]); p.y = fp16q(xs[3]);
                *(ushort2*)&Ah[r2][cc] = p;
            }
        }
    };

    const float inv64 = 0.125f;
    stageB(gW2H, gW2L, 0);
    __syncthreads();
    zacc(); mmaAB();
    __syncthreads();
    epiH(inv64);
    stageB(gW3H, gW3L, 0);
    __syncthreads();
    zacc(); mmaAB();
    __syncthreads();
    epiH(inv64);
    __syncthreads();

    for (int n0 = 0; n0 < 512; n0 += 64) {
        stageB(gW4H, gW4L, n0);
        __syncthreads();
        zacc(); mmaAB();

        if (n0 < 256) {
            __syncthreads();
            // multiply T-chunk accumulators by gather factor -> Ao (fp16)
#pragma unroll
            for (int mt = 0; mt < 2; mt++) {
#pragma unroll
                for (int hrow = 0; hrow < 2; hrow++) {
                    int rloc = am + mt * 16 + g + hrow * 8;
                    int snd = sSnd[rloc];
                    float4 y = sY[rloc];
#pragma unroll
                    for (int nt = 0; nt < 4; nt++) {
                        int cc = bn + nt * 8 + tg * 2;
                        int k = n0 + cc;
                        float f0, f1;
                        if (n0 < 128) {
                            const float* sp = gS + (size_t)snd * 128 + k;
                            f0 = sp[0] * y.x; f1 = sp[1] * y.x;
                        } else {
                            int u = k - 128;
                            const float* vp = gV + (size_t)snd * 384 + u;
                            f0 = (vp[0] * y.y + vp[128] * y.z + vp[256] * y.w) * 0.57735026918962576f;
                            f1 = (vp[1] * y.y + vp[129] * y.z + vp[257] * y.w) * 0.57735026918962576f;
                        }
                        float a0 = acc[mt][nt][2 * hrow + 0] * inv64 * f0;
                        float a1 = acc[mt][nt][2 * hrow + 1] * inv64 * f1;
                        ushort2 p; p.x = fp16q(a0); p.y = fp16q(a1);
                        *(ushort2*)&Ao[rloc][cc] = p;
                    }
                }
            }
            // stage Ws chunk [128 N][64 K] -> Bw rows 0..127
#pragma unroll
            for (int i = 0; i < 8; i++) {
                int idx = tid + i * 128;
                int r = idx >> 3, c8 = (idx & 7) * 8;
                *(uint4*)&Bw[r][c8] = *(const uint4*)(gWsH + (size_t)r * 256 + n0 + c8);
            }
            __syncthreads();
#pragma unroll
            for (int ks = 0; ks < 4; ks++) {
                unsigned ah[2][4];
#pragma unroll
                for (int mt = 0; mt < 2; mt++)
                    ldsm4(ah[mt], aO + mt * (16 * RB) + ks * 32);
#pragma unroll
                for (int n2 = 0; n2 < 2; n2++) {
                    unsigned bh[2][4];
#pragma unroll
                    for (int np = 0; np < 2; np++)
                        ldsm4(bh[np], bH + n2 * (64 * RB) + np * (16 * RB) + ks * 32);
#pragma unroll
                    for (int mt = 0; mt < 2; mt++)
#pragma unroll
                        for (int nt = 0; nt < 4; nt++)
                            mma_f16(acco[n2][mt][nt], ah[mt], &bh[nt >> 1][(nt & 1) * 2]);
                }
            }
            __syncthreads();
        } else {
#pragma unroll
            for (int mt = 0; mt < 2; mt++) {
                int r1 = row0 + am + mt * 16 + g, r2 = r1 + 8;
#pragma unroll
                for (int nt = 0; nt < 4; nt++) {
                    int cc = bn + nt * 8 + tg * 2;
                    if (r1 < NE) {
                        ushort2 p; p.x = fp16q(acc[mt][nt][0] * inv64);
                        p.y = fp16q(acc[mt][nt][1] * inv64);
                        *(ushort2*)&gTH[(size_t)r1 * 512 + n0 + cc] = p;
                    }
                    if (r2 < NE) {
                        ushort2 p; p.x = fp16q(acc[mt][nt][2] * inv64);
                        p.y = fp16q(acc[mt][nt][3] * inv64);
                        *(ushort2*)&gTH[(size_t)r2 * 512 + n0 + cc] = p;
                    }
                }
            }
            __syncthreads();
        }
    }

    // ---- out_s epilogue: C[:, :128] ----
#pragma unroll
    for (int n2 = 0; n2 < 2; n2++) {
#pragma unroll
        for (int mt = 0; mt < 2; mt++) {
            int rr[2]; rr[0] = row0 + am + mt * 16 + g; rr[1] = rr[0] + 8;
#pragma unroll
            for (int nt = 0; nt < 4; nt++) {
                int cc = n2 * 64 + bn + nt * 8 + tg * 2;
#pragma unroll
                for (int h = 0; h < 2; h++) {
                    int gr = rr[h];
                    if (gr >= NE) continue;
                    float x0 = acco[n2][mt][nt][2 * h] * 0.0625f;
                    float x1 = acco[n2][mt][nt][2 * h + 1] * 0.0625f;
                    *(float2*)&C[(size_t)gr * 512 + cc] = make_float2(x0, x1);
                }
            }
        }
    }
}

// ---------------- fused out_v (direct scatter epilogue) ------------------------
__global__ __launch_bounds__(256, 2) void mma_outv(
        const void* __restrict__ eidx, const float* __restrict__ eattr,
        float* __restrict__ C) {
    const int PK = 40;
    __shared__ __align__(16) ushort_t Ah[128][PK];
    __shared__ __align__(16) ushort_t Bhs[128][PK];
    __shared__ int sSnd[128];
    __shared__ float sY0[128], sYm[128];

    int tid = threadIdx.x;
    int wid = tid >> 5, lane = tid & 31;
    int warp_m = wid & 3, warp_n = wid >> 2;
    int g = lane >> 2, tg = lane & 3;
    int row0 = blockIdx.x * 128;
    int am = warp_m * 32, bn = warp_n * 32;

    if (tid < 128) {
        int gr = min(row0 + tid, 3 * NE - 1);
        int e = gr / 3, m = gr - 3 * e;
        int snd = gIdx64 ? (int)((const long long*)eidx)[e] : ((const int*)eidx)[e];
        sSnd[tid] = min(max(snd, 0), NN - 1);
        float4 y = *(const float4*)(eattr + 4 * e);
        sY0[tid] = y.x;
        sYm[tid] = (m == 0) ? y.y : ((m == 1) ? y.z : y.w);
    }
    __syncthreads();

    int arow = (lane & 7) + ((lane >> 3) & 1) * 8;
    int acol = (lane >> 4) * 8;
    uint32_t aH = smem_u32(&Ah[am + arow][acol]);
    int brow = (lane & 7) + ((lane >> 4) & 1) * 8;
    int bcol = ((lane >> 3) & 1) * 8;
    uint32_t bH = smem_u32(&Bhs[bn + brow][bcol]);

    float acc[2][2][4][4];
#pragma unroll
    for (int n2 = 0; n2 < 2; n2++)
#pragma unroll
        for (int mt = 0; mt < 2; mt++)
#pragma unroll
            for (int nt = 0; nt < 4; nt++)
#pragma unroll
                for (int j = 0; j < 4; j++) acc[n2][mt][nt][j] = 0.f;

    int r = tid >> 1, half = tid & 1;
    int grr = min(row0 + r, 3 * NE - 1);
    int e = grr / 3, m = grr - 3 * e;
    int snd = sSnd[r];
    float y0 = sY0[r], ym = sYm[r];

    auto computeA = [&](int kc, ushort_t* hh) {
        int u0 = (kc & 3) * 32 + half * 16;
        size_t tb = (size_t)e * 512 + (kc < 4 ? 256 : 384) + u0;
        __align__(16) ushort_t th[16];
        *(uint4*)&th[0] = *(const uint4*)(gTH + tb);
        *(uint4*)&th[8] = *(const uint4*)(gTH + tb + 8);
        if (kc < 4) {
            const float* sp = gS + (size_t)snd * 128 + u0;
#pragma unroll
            for (int j = 0; j < 16; j++)
                hh[j] = fp16q(fp2f(th[j]) * sp[j] * ym);
        } else {
            const float* vp = gV + (size_t)snd * 384 + m * 128 + u0;
#pragma unroll
            for (int j = 0; j < 16; j++)
                hh[j] = fp16q(fp2f(th[j]) * y0 * vp[j]);
        }
    };

    __align__(16) ushort_t hc[16], hn[16];
    computeA(0, hc);

    for (int kc = 0; kc < 8; kc++) {
        *(uint4*)&Ah[r][half * 16] = *(uint4*)&hc[0];
        *(uint4*)&Ah[r][half * 16 + 8] = *(uint4*)&hc[8];
        {
            const ushort_t* ph = gWvH + (size_t)r * 256 + kc * 32 + half * 16;
            *(uint4*)&Bhs[r][half * 16] = *(const uint4*)ph;
            *(uint4*)&Bhs[r][half * 16 + 8] = *(const uint4*)(ph + 8);
        }
        __syncthreads();
        if (kc < 7) computeA(kc + 1, hn);

#pragma unroll
        for (int ks = 0; ks < 2; ks++) {
            unsigned ah[2][4];
#pragma unroll
            for (int mt = 0; mt < 2; mt++)
                ldsm4(ah[mt], aH + mt * (16 * PK * 2) + ks * 32);
#pragma unroll
            for (int n2 = 0; n2 < 2; n2++) {
                unsigned bh[2][4];
#pragma unroll
                for (int np = 0; np < 2; np++)
                    ldsm4(bh[np], bH + n2 * (64 * PK * 2) + np * (16 * PK * 2) + ks * 32);
#pragma unroll
                for (int mt = 0; mt < 2; mt++)
#pragma unroll
                    for (int nt = 0; nt < 4; nt++)
                        mma_f16(acc[n2][mt][nt], ah[mt], &bh[nt >> 1][(nt & 1) * 2]);
            }
        }
        __syncthreads();
#pragma unroll
        for (int j = 0; j < 16; j++) hc[j] = hn[j];
    }

#pragma unroll
    for (int n2 = 0; n2 < 2; n2++) {
#pragma unroll
        for (int mt = 0; mt < 2; mt++) {
            int rr[2]; rr[0] = row0 + am + mt * 16 + g; rr[1] = rr[0] + 8;
#pragma unroll
            for (int nt = 0; nt < 4; nt++) {
                int cc = n2 * 64 + bn + nt * 8 + tg * 2;
#pragma unroll
                for (int h = 0; h < 2; h++) {
                    int gr = rr[h];
                    if (gr >= 3 * NE) continue;
                    int ee = gr / 3, mm = gr - 3 * ee;
                    float x0 = acc[n2][mt][nt][2 * h] * 0.0625f;
                    float x1 = acc[n2][mt][nt][2 * h + 1] * 0.0625f;
                    C[(size_t)ee * 512 + 128 + mm + 3 * cc] = x0;
                    C[(size_t)ee * 512 + 128 + mm + 3 * (cc + 1)] = x1;
                }
            }
        }
    }
}

// ---------------- launch ----------------
extern "C" void kernel_launch(void* const* d_in, const int* in_sizes, int n_in,
                              void* d_out, int out_size) {
    const float* node_feats = (const float*)d_in[0];
    const void*  edge_index = d_in[1];
    const float* edge_attrs = (const float*)d_in[2];
    const float* edge_feats = (const float*)d_in[3];
    const float* W_up_s     = (const float*)d_in[4];
    const float* W_up_v     = (const float*)d_in[5];
    const float* W1         = (const float*)d_in[6];
    const float* W2         = (const float*)d_in[7];
    const float* W3         = (const float*)d_in[8];
    const float* W4         = (const float*)d_in[9];
    const float* W_out_s    = (const float*)d_in[10];
    const float* W_out_v    = (const float*)d_in[11];
    float* out = (float*)d_out;

    // SILU_CST on host (same trapezoid as reference; runs at capture)
    double I = 0.0;
    for (int i = 0; i <= 200000; i++) {
        double z = -12.0 + 24.0 * ((double)i / 200000.0);
        double pdf = exp(-0.5 * z * z) * 0.3989422804014326779399461;
        double s = z / (1.0 + exp(-z));
        double f = s * s * pdf;
        I += (i == 0 || i == 200000) ? 0.5 * f : f;
    }
    I *= 24.0 / 200000.0;
    float cstF = (float)(1.0 / sqrt(I));

    cudaFuncSetAttribute(mlp_outs_fused, cudaFuncAttributeMaxDynamicSharedMemorySize, FUSE_SMEM);

    detect_idx_kernel<<<1, 32>>>((const int*)edge_index);
    prep_all<<<dim3(128, 5), 256>>>(W2, W3, W4, W_out_s, W_out_v);
    node_up<<<dim3(157, 2, 4), 256>>>(node_feats, W_up_s, W_up_v);
    mlp_outs_fused<<<3125, 128, FUSE_SMEM>>>(edge_feats, W1, edge_index, edge_attrs,
                                             out, cstF);
    mma_outv<<<4688, 256>>>(edge_index, edge_attrs, out);
    (void)in_sizes; (void)n_in; (void)out_size;
}